// round 2
// baseline (speedup 1.0000x reference)
#include <cuda_runtime.h>
#include <math.h>
#include <stdint.h>

#define B_    1024
#define T_    512
#define BT_   (B_*T_)
#define IND   64
#define HD    128
#define G3    384
#define OD    64
#define NEG   0.01f
#define LNEPS 1e-5f

// ---------------- scratch (device globals: allocation-free rule) ----------------
static __device__ float g_gates[(size_t)BT_ * G3];   // [B*T, 384]
static __device__ float g_y[(size_t)BT_ * HD];       // [B*T, 128]
static __device__ int   g_wordmode;                  // 1: is_init is 4-byte words, 0: bytes

// Detect is_init storage: words that are all in {0,1,0x3F800000} => int32/float32 (word mode),
// otherwise raw bool bytes. Deterministic pure function of the input buffer.
__global__ void detect_kernel(const unsigned int* __restrict__ p) {
    if (threadIdx.x == 0) {
        int wm = 1;
        for (int i = 0; i < 256; i++) {
            unsigned v = p[i];
            if (v != 0u && v != 1u && v != 0x3F800000u) { wm = 0; break; }
        }
        g_wordmode = wm;
    }
}

// ---------------- feed-forward kernel helpers ----------------
// GEMM: dst[j][tok] = leaky(src^T @ W^T + bias), K-major smem buffers padded to 68 floats/row.
template<int K>
__device__ inline void gemm_to_smem(const float (*src)[68], const float* __restrict__ W,
                                    const float* __restrict__ bias, float (*dst)[68],
                                    float (*Ws)[68], int tid)
{
    for (int nc = 0; nc < HD; nc += 64) {
        __syncthreads();
        for (int idx = tid; idx < 64 * K; idx += 256) {
            int j = idx / K, k = idx - j * K;
            Ws[k][j] = W[(size_t)nc * K + idx];
        }
        __syncthreads();
        const int tok0 = (tid & 15) << 2, col0 = (tid >> 4) << 2;
        float acc[4][4] = {};
        #pragma unroll 4
        for (int k = 0; k < K; k++) {
            float4 a = *(const float4*)&src[k][tok0];
            float4 b = *(const float4*)&Ws[k][col0];
            acc[0][0] += a.x*b.x; acc[0][1] += a.x*b.y; acc[0][2] += a.x*b.z; acc[0][3] += a.x*b.w;
            acc[1][0] += a.y*b.x; acc[1][1] += a.y*b.y; acc[1][2] += a.y*b.z; acc[1][3] += a.y*b.w;
            acc[2][0] += a.z*b.x; acc[2][1] += a.z*b.y; acc[2][2] += a.z*b.z; acc[2][3] += a.z*b.w;
            acc[3][0] += a.w*b.x; acc[3][1] += a.w*b.y; acc[3][2] += a.w*b.z; acc[3][3] += a.w*b.w;
        }
        #pragma unroll
        for (int ci = 0; ci < 4; ci++) {
            int j = nc + col0 + ci;
            float bb = bias[j];
            float4 v;
            v.x = acc[0][ci] + bb; v.y = acc[1][ci] + bb;
            v.z = acc[2][ci] + bb; v.w = acc[3][ci] + bb;
            v.x = v.x > 0.f ? v.x : NEG * v.x;
            v.y = v.y > 0.f ? v.y : NEG * v.y;
            v.z = v.z > 0.f ? v.z : NEG * v.z;
            v.w = v.w > 0.f ? v.w : NEG * v.w;
            *(float4*)&dst[j][tok0] = v;
        }
    }
    __syncthreads();
}

__device__ inline void layernorm(float (*buf)[68], const float* __restrict__ gam,
                                 const float* __restrict__ bet, int tid)
{
    int tok = tid >> 2, part = tid & 3;
    float s = 0.f, ss = 0.f;
    #pragma unroll
    for (int i = 0; i < 32; i++) {
        float v = buf[part * 32 + i][tok];
        s += v; ss += v * v;
    }
    s  += __shfl_xor_sync(0xffffffffu, s, 1);  s  += __shfl_xor_sync(0xffffffffu, s, 2);
    ss += __shfl_xor_sync(0xffffffffu, ss, 1); ss += __shfl_xor_sync(0xffffffffu, ss, 2);
    float mu   = s * (1.f / HD);
    float var  = ss * (1.f / HD) - mu * mu;
    float rstd = rsqrtf(var + LNEPS);
    #pragma unroll
    for (int i = 0; i < 32; i++) {
        int j = part * 32 + i;
        float v = buf[j][tok];
        buf[j][tok] = (v - mu) * rstd * gam[j] + bet[j];
    }
    __syncthreads();
}

__device__ inline void gemm3_to_global(const float (*src)[68], const float* __restrict__ W,
                                       const float* __restrict__ bias, float* __restrict__ gout,
                                       float (*Ws)[68], int tid, size_t base)
{
    for (int nc = 0; nc < G3; nc += 64) {
        __syncthreads();
        for (int idx = tid; idx < 64 * HD; idx += 256) {
            int j = idx >> 7, k = idx & 127;
            Ws[k][j] = W[(size_t)nc * HD + idx];
        }
        __syncthreads();
        const int tok0 = (tid & 15) << 2, col0 = (tid >> 4) << 2;
        float acc[4][4] = {};
        #pragma unroll 4
        for (int k = 0; k < HD; k++) {
            float4 a = *(const float4*)&src[k][tok0];
            float4 b = *(const float4*)&Ws[k][col0];
            acc[0][0] += a.x*b.x; acc[0][1] += a.x*b.y; acc[0][2] += a.x*b.z; acc[0][3] += a.x*b.w;
            acc[1][0] += a.y*b.x; acc[1][1] += a.y*b.y; acc[1][2] += a.y*b.z; acc[1][3] += a.y*b.w;
            acc[2][0] += a.z*b.x; acc[2][1] += a.z*b.y; acc[2][2] += a.z*b.z; acc[2][3] += a.z*b.w;
            acc[3][0] += a.w*b.x; acc[3][1] += a.w*b.y; acc[3][2] += a.w*b.z; acc[3][3] += a.w*b.w;
        }
        int col = nc + col0;
        float b0 = bias[col], b1 = bias[col+1], b2 = bias[col+2], b3 = bias[col+3];
        #pragma unroll
        for (int ti = 0; ti < 4; ti++) {
            float4 v;
            v.x = acc[ti][0] + b0; v.y = acc[ti][1] + b1;
            v.z = acc[ti][2] + b2; v.w = acc[ti][3] + b3;
            *(float4*)&gout[(base + tok0 + ti) * G3 + col] = v;
        }
    }
}

// ---------------- FF kernel: x -> MLP1 -> LN -> MLP2 -> LN -> W_ih gates ----------------
__global__ void __launch_bounds__(256, 2) ff_kernel(
    const float* __restrict__ x,
    const float* __restrict__ W1, const float* __restrict__ b1,
    const float* __restrict__ g1, const float* __restrict__ be1,
    const float* __restrict__ W2, const float* __restrict__ b2,
    const float* __restrict__ g2, const float* __restrict__ be2,
    const float* __restrict__ Wih, const float* __restrict__ bih)
{
    extern __shared__ float sm[];
    float (*A)[68]  = (float(*)[68])sm;                  // 128x68
    float (*Bb)[68] = (float(*)[68])(sm + 128 * 68);     // 128x68
    float (*Ws)[68] = (float(*)[68])(sm + 2 * 128 * 68); // 128x68
    int tid = threadIdx.x;
    size_t base = (size_t)blockIdx.x * 64;

    // load x tile K-major: A[k][tok]
    for (int idx = tid; idx < 64 * IND; idx += 256) {
        int tok = idx >> 6, k = idx & 63;
        A[k][tok] = x[base * IND + idx];
    }
    gemm_to_smem<IND>(A, W1, b1, Bb, Ws, tid);
    layernorm(Bb, g1, be1, tid);
    gemm_to_smem<HD>(Bb, W2, b2, A, Ws, tid);
    layernorm(A, g2, be2, tid);
    gemm3_to_global(A, Wih, bih, g_gates, Ws, tid, base);
}

// ---------------- recurrent kernel: persistent over T, 8 sequences/block ----------------
__global__ void __launch_bounds__(512, 1) rec_kernel(
    const float* __restrict__ hx, const float* __restrict__ Whh,
    const float* __restrict__ bhh, const void* __restrict__ isinit,
    float* __restrict__ hxout)
{
    __shared__ float hs[2][8][HD];
    __shared__ float gx[8][G3];
    __shared__ int initf[8];
    const int tid = threadIdx.x;
    const int r = tid >> 2, c = tid & 3;           // row r, k-chunk c (32 wide)
    const int b0 = blockIdx.x * 8;

    // register-resident W_hh: rows r, r+128, r+256, k in [c*32, c*32+32)
    float w0[32], w1[32], w2[32];
    {
        const float* p0 = Whh + (size_t)r * HD + c * 32;
        const float* p1 = Whh + (size_t)(r + 128) * HD + c * 32;
        const float* p2 = Whh + (size_t)(r + 256) * HD + c * 32;
        #pragma unroll
        for (int i = 0; i < 32; i += 4) {
            float4 t0 = *(const float4*)(p0 + i);
            w0[i] = t0.x; w0[i+1] = t0.y; w0[i+2] = t0.z; w0[i+3] = t0.w;
            float4 t1 = *(const float4*)(p1 + i);
            w1[i] = t1.x; w1[i+1] = t1.y; w1[i+2] = t1.z; w1[i+3] = t1.w;
            float4 t2 = *(const float4*)(p2 + i);
            w2[i] = t2.x; w2[i+1] = t2.y; w2[i+2] = t2.z; w2[i+3] = t2.w;
        }
    }
    const float bh0 = (c == 0) ? bhh[r]       : 0.f;
    const float bh1 = (c == 0) ? bhh[r + 128] : 0.f;
    const float bh2 = (c == 0) ? bhh[r + 256] : 0.f;

    for (int idx = tid; idx < 8 * HD; idx += 512)
        hs[0][idx >> 7][idx & 127] = hx[(size_t)b0 * HD + idx];

    const int wm = g_wordmode;
    const unsigned int*  ii32 = (const unsigned int*)isinit;
    const unsigned char* ii8  = (const unsigned char*)isinit;

    int cur = 0;
    for (int t = 0; t < T_; t++) {
        // stage gates_x for this timestep (8 batch x 384), coalesced
        #pragma unroll
        for (int rep = 0; rep < 6; rep++) {
            int flat = rep * 512 + tid;
            int b = flat / G3, j = flat - b * G3;
            gx[b][j] = g_gates[((size_t)(b0 + b) * T_ + t) * G3 + j];
        }
        if (tid < 8) {
            size_t ix = (size_t)(b0 + tid) * T_ + t;
            initf[tid] = wm ? (ii32[ix] != 0u) : (ii8[ix] != 0);
        }
        __syncthreads();

        const int nxt = cur ^ 1;
        #pragma unroll 1
        for (int b = 0; b < 8; b++) {
            float a0 = bh0, a1 = bh1, a2 = bh2;
            const int fi = initf[b];
            if (!fi) {
                const float* hp = &hs[cur][b][c * 32];
                #pragma unroll
                for (int i = 0; i < 32; i += 4) {
                    float4 h4 = *(const float4*)(hp + i);
                    a0 = fmaf(w0[i], h4.x, a0); a0 = fmaf(w0[i+1], h4.y, a0);
                    a0 = fmaf(w0[i+2], h4.z, a0); a0 = fmaf(w0[i+3], h4.w, a0);
                    a1 = fmaf(w1[i], h4.x, a1); a1 = fmaf(w1[i+1], h4.y, a1);
                    a1 = fmaf(w1[i+2], h4.z, a1); a1 = fmaf(w1[i+3], h4.w, a1);
                    a2 = fmaf(w2[i], h4.x, a2); a2 = fmaf(w2[i+1], h4.y, a2);
                    a2 = fmaf(w2[i+2], h4.z, a2); a2 = fmaf(w2[i+3], h4.w, a2);
                }
            }
            a0 += __shfl_xor_sync(0xffffffffu, a0, 1); a0 += __shfl_xor_sync(0xffffffffu, a0, 2);
            a1 += __shfl_xor_sync(0xffffffffu, a1, 1); a1 += __shfl_xor_sync(0xffffffffu, a1, 2);
            a2 += __shfl_xor_sync(0xffffffffu, a2, 1); a2 += __shfl_xor_sync(0xffffffffu, a2, 2);
            if (c == 0) {
                float hp = fi ? 0.f : hs[cur][b][r];
                float xr = gx[b][r], xz = gx[b][r + 128], xn = gx[b][r + 256];
                float rr = 1.f / (1.f + __expf(-(xr + a0)));
                float zz = 1.f / (1.f + __expf(-(xz + a1)));
                float nn = tanhf(xn + rr * a2);
                hs[nxt][b][r] = (1.f - zz) * nn + zz * hp;
            }
        }
        __syncthreads();

        // write y for this timestep, coalesced
        #pragma unroll
        for (int rep = 0; rep < 2; rep++) {
            int flat = rep * 512 + tid;
            int b = flat >> 7, k = flat & 127;
            g_y[((size_t)(b0 + b) * T_ + t) * HD + k] = hs[nxt][b][k];
        }
        cur = nxt;
    }
    for (int idx = tid; idx < 8 * HD; idx += 512)
        hxout[(size_t)b0 * HD + idx] = hs[cur][idx >> 7][idx & 127];
}

// ---------------- output projection: out = y @ W_out^T + b_out ----------------
__global__ void __launch_bounds__(256, 2) out_kernel(
    const float* __restrict__ Wout, const float* __restrict__ bout,
    float* __restrict__ out)
{
    extern __shared__ float sm[];
    float (*A)[68]  = (float(*)[68])sm;              // y tile, K-major
    float (*Ws)[68] = (float(*)[68])(sm + 128 * 68); // W_out^T
    int tid = threadIdx.x;
    size_t base = (size_t)blockIdx.x * 64;

    for (int idx = tid; idx < 64 * HD; idx += 256) {
        int tok = idx >> 7, k = idx & 127;
        A[k][tok] = g_y[base * HD + idx];
    }
    for (int idx = tid; idx < OD * HD; idx += 256) {
        int j = idx >> 7, k = idx & 127;
        Ws[k][j] = Wout[idx];
    }
    __syncthreads();

    const int tok0 = (tid & 15) << 2, col0 = (tid >> 4) << 2;
    float acc[4][4] = {};
    #pragma unroll 4
    for (int k = 0; k < HD; k++) {
        float4 a = *(const float4*)&A[k][tok0];
        float4 b = *(const float4*)&Ws[k][col0];
        acc[0][0] += a.x*b.x; acc[0][1] += a.x*b.y; acc[0][2] += a.x*b.z; acc[0][3] += a.x*b.w;
        acc[1][0] += a.y*b.x; acc[1][1] += a.y*b.y; acc[1][2] += a.y*b.z; acc[1][3] += a.y*b.w;
        acc[2][0] += a.z*b.x; acc[2][1] += a.z*b.y; acc[2][2] += a.z*b.z; acc[2][3] += a.z*b.w;
        acc[3][0] += a.w*b.x; acc[3][1] += a.w*b.y; acc[3][2] += a.w*b.z; acc[3][3] += a.w*b.w;
    }
    float b0 = bout[col0], b1 = bout[col0+1], b2 = bout[col0+2], b3 = bout[col0+3];
    #pragma unroll
    for (int ti = 0; ti < 4; ti++) {
        float4 v;
        v.x = acc[ti][0] + b0; v.y = acc[ti][1] + b1;
        v.z = acc[ti][2] + b2; v.w = acc[ti][3] + b3;
        *(float4*)&out[(base + tok0 + ti) * OD + col0] = v;
    }
}

// ---------------- launcher ----------------
extern "C" void kernel_launch(void* const* d_in, const int* in_sizes, int n_in,
                              void* d_out, int out_size)
{
    const float* x    = (const float*)d_in[0];
    const void*  isin = d_in[1];
    const float* hx   = (const float*)d_in[2];
    const float* W1   = (const float*)d_in[3];
    const float* b1   = (const float*)d_in[4];
    const float* g1   = (const float*)d_in[5];
    const float* be1  = (const float*)d_in[6];
    const float* W2   = (const float*)d_in[7];
    const float* b2   = (const float*)d_in[8];
    const float* g2   = (const float*)d_in[9];
    const float* be2  = (const float*)d_in[10];
    const float* Wih  = (const float*)d_in[11];
    const float* Whh  = (const float*)d_in[12];
    const float* bih  = (const float*)d_in[13];
    const float* bhh  = (const float*)d_in[14];
    const float* Wout = (const float*)d_in[15];
    const float* bout = (const float*)d_in[16];
    float* out = (float*)d_out;

    const int SM_FF  = 3 * 128 * 68 * (int)sizeof(float);
    const int SM_OUT = 2 * 128 * 68 * (int)sizeof(float);
    cudaFuncSetAttribute(ff_kernel,  cudaFuncAttributeMaxDynamicSharedMemorySize, SM_FF);
    cudaFuncSetAttribute(out_kernel, cudaFuncAttributeMaxDynamicSharedMemorySize, SM_OUT);

    detect_kernel<<<1, 32>>>((const unsigned int*)isin);
    ff_kernel<<<BT_ / 64, 256, SM_FF>>>(x, W1, b1, g1, be1, W2, b2, g2, be2, Wih, bih);
    rec_kernel<<<B_ / 8, 512>>>(hx, Whh, bhh, isin, out + (size_t)BT_ * OD);
    out_kernel<<<BT_ / 64, 256, SM_OUT>>>(Wout, bout, out);
}